// round 1
// baseline (speedup 1.0000x reference)
#include <cuda_runtime.h>
#include <cuda_bf16.h>

// SubglacialDrainageSystem: L x = f where L is a 5-point-stencil operator on a
// 64x64 grid (half-bandwidth 64) with identity rows at inflow nodes.
// Strategy: assemble banded matrix in fp64 -> no-pivot band LU (stable: weakly
// diagonally dominant M-matrix) in a single CTA -> warp-serial band solves.

#define NN 4096
#define BW 64
#define WPAD 132   // band row width (129 used), padded

static __device__ double g_band[(size_t)NN * WPAD];
static __device__ double g_rhs[NN];

// ---------------------------------------------------------------------------
// Kernel 1: assembly. One thread per node.
// ---------------------------------------------------------------------------
__global__ void assemble_kernel(const float* __restrict__ h,
                                const float* __restrict__ phi,
                                const float* __restrict__ base,
                                const float* __restrict__ over,
                                const float* __restrict__ melt,
                                const float* __restrict__ len,
                                const int*   __restrict__ adj,
                                const int*   __restrict__ io)
{
    int i = blockIdx.x * blockDim.x + threadIdx.x;
    if (i >= NN) return;

    double* row = &g_band[(size_t)i * WPAD];
#pragma unroll 4
    for (int t = 0; t < WPAD; t++) row[t] = 0.0;

    const bool is_inflow = (io[i] == 1);
    const double hi = (double)h[i];
    const double pi = (double)phi[i];
    double diag = 0.0;

#pragma unroll
    for (int k = 0; k < 4; k++) {
        int   j = adj[i * 4 + k];
        float L = len[i * 4 + k];
        if (j >= 0 && L > 0.0f && !is_inflow) {
            double hf   = 0.5 * (hi + (double)h[j]);
            double dphi = fabs(pi - (double)phi[j]);
            double g    = fmax(dphi, 1e-12) / (double)L;
            // coeff = -K * hf^1.25 * L * g^{-1/2},  K = 0.01
            double coeff = -0.01 * pow(hf, 1.25) * (double)L * rsqrt(g);
            row[j - i + 64] = coeff;     // j-i in {+-1, +-64}
            diag -= coeff;
        }
    }
    row[64] = is_inflow ? 1.0 : diag;
    g_rhs[i] = is_inflow ? ((double)base[i] - (double)over[i]) : (double)melt[i];
}

// ---------------------------------------------------------------------------
// Kernel 2: single-CTA band LU (no pivoting) + forward/back substitution.
// ---------------------------------------------------------------------------
__global__ void __launch_bounds__(1024, 1)
band_lu_solve_kernel(float* __restrict__ out)
{
    __shared__ double s_l[BW];
    __shared__ double s_u[BW];
    __shared__ double s_y[NN];       // 32 KB: solution vector workspace
    const int tid = threadIdx.x;

    // ---- Factorization: A = L U within the band --------------------------
    for (int k = 0; k < NN - 1; k++) {
        int m = NN - 1 - k;
        if (m > BW) m = BW;

        if (tid < m) {
            double piv = g_band[(size_t)k * WPAD + 64];
            size_t li  = (size_t)(k + 1 + tid) * WPAD + (63 - tid); // col k entry
            double l   = g_band[li] / piv;
            g_band[li] = l;                       // store multiplier (L)
            s_l[tid]   = l;
            s_u[tid]   = g_band[(size_t)k * WPAD + 65 + tid];       // row k (U)
        }
        __syncthreads();

        // trailing m x m update: A[k+1+ii][k+1+jj] -= l_ii * u_jj
        for (int e = tid; e < m * m; e += 1024) {
            int ii = e / m;
            int jj = e - ii * m;
            g_band[(size_t)(k + 1 + ii) * WPAD + (jj - ii + 64)] -= s_l[ii] * s_u[jj];
        }
        __syncthreads();
    }

    // ---- Substitution by warp 0 (band solves are inherently sequential) --
    if (tid < 32) {
        // forward: y = L^{-1} b   (L unit lower)
        for (int i = 0; i < NN; i++) {
            double s = 0.0;
            int lo = i - BW; if (lo < 0) lo = 0;
            for (int mm = lo + tid; mm < i; mm += 32)
                s += g_band[(size_t)i * WPAD + (mm - i + 64)] * s_y[mm];
#pragma unroll
            for (int o = 16; o; o >>= 1) s += __shfl_down_sync(0xffffffffu, s, o);
            if (tid == 0) s_y[i] = g_rhs[i] - s;
            __syncwarp();
        }
        // backward: x = U^{-1} y  (in place over s_y)
        for (int i = NN - 1; i >= 0; i--) {
            double s = 0.0;
            int hi2 = i + BW; if (hi2 > NN - 1) hi2 = NN - 1;
            for (int mm = i + 1 + tid; mm <= hi2; mm += 32)
                s += g_band[(size_t)i * WPAD + (mm - i + 64)] * s_y[mm];
#pragma unroll
            for (int o = 16; o; o >>= 1) s += __shfl_down_sync(0xffffffffu, s, o);
            if (tid == 0) s_y[i] = (s_y[i] - s) / g_band[(size_t)i * WPAD + 64];
            __syncwarp();
        }
    }
    __syncthreads();

    for (int i = tid; i < NN; i += 1024) out[i] = (float)s_y[i];
}

// ---------------------------------------------------------------------------
// kernel_launch
// inputs: 0 sheet_thickness, 1 previous_potential, 2 base_potential,
//         3 overburden_pressure, 4 specific_melt_rate, 5 link_length[N,4],
//         6 adjacent_nodes[N,4], 7 inflow_outflow[N]
// output: float[4096]
// ---------------------------------------------------------------------------
extern "C" void kernel_launch(void* const* d_in, const int* in_sizes, int n_in,
                              void* d_out, int out_size)
{
    const float* h    = (const float*)d_in[0];
    const float* phi  = (const float*)d_in[1];
    const float* base = (const float*)d_in[2];
    const float* over = (const float*)d_in[3];
    const float* melt = (const float*)d_in[4];
    const float* len  = (const float*)d_in[5];
    const int*   adj  = (const int*)  d_in[6];
    const int*   io   = (const int*)  d_in[7];
    float* out = (float*)d_out;

    assemble_kernel<<<(NN + 255) / 256, 256>>>(h, phi, base, over, melt, len, adj, io);
    band_lu_solve_kernel<<<1, 1024>>>(out);
}

// round 3
// speedup vs baseline: 28.1807x; 28.1807x over previous
#include <cuda_runtime.h>
#include <cuda_bf16.h>

// SubglacialDrainageSystem: L x = f on a 64x64 grid.
// Block-tridiagonal structure: 64 block rows r, each 64 unknowns.
//   C_r x_{r-1} + A_r x_r + B_r x_{r+1} = y_r
// A_r tridiagonal (west/east links), B_r / C_r diagonal (south/north links),
// identity rows at inflow nodes. Solved by block cyclic reduction (6 levels)
// in fp32: per level, eliminated rows j get Z_j = A_j^{-1}[C_j|B_j|y_j] via
// register-resident Gauss-Jordan (one CTA per block), then Schur updates of
// the remaining rows via 64x64x64 GEMM CTAs. Backsub in a single CTA.

#define NBLK 64
#define BD   64          // block dimension
#define BSZ  (BD * BD)   // 4096 floats per block

static __device__ float gA [NBLK * BSZ];       // diagonal blocks (in-place)
static __device__ float gCb[2][NBLK * BSZ];    // sub-diag blocks, ping-pong
static __device__ float gBb[2][NBLK * BSZ];    // super-diag blocks, ping-pong
static __device__ float gy [NBLK * BD];        // rhs (in-place)
static __device__ float gZC[NBLK * BSZ];       // A^{-1} C per eliminated row
static __device__ float gZB[NBLK * BSZ];       // A^{-1} B
static __device__ float gZy[NBLK * BD];        // A^{-1} y

// ---------------------------------------------------------------------------
// Assembly: one thread per node. fp64 coefficient math (matches reference),
// fp32 storage. Each thread zeroes and fills its own block row slice.
// ---------------------------------------------------------------------------
__global__ void assemble_kernel(const float* __restrict__ h,
                                const float* __restrict__ phi,
                                const float* __restrict__ base,
                                const float* __restrict__ over,
                                const float* __restrict__ melt,
                                const float* __restrict__ len,
                                const int*   __restrict__ adj,
                                const int*   __restrict__ io)
{
    int i = blockIdx.x * blockDim.x + threadIdx.x;
    if (i >= NBLK * BD) return;
    int r = i >> 6, a = i & 63;

    float4 z = make_float4(0.f, 0.f, 0.f, 0.f);
    float4* rowA = (float4*)(gA     + r * BSZ + a * BD);
    float4* rowC = (float4*)(gCb[0] + r * BSZ + a * BD);
    float4* rowB = (float4*)(gBb[0] + r * BSZ + a * BD);
#pragma unroll
    for (int b = 0; b < 16; b++) { rowA[b] = z; rowC[b] = z; rowB[b] = z; }

    const bool infl = (io[i] == 1);
    const double hi = (double)h[i];
    const double pi = (double)phi[i];
    double diag = 0.0;
    double cf0 = 0.0, cf1 = 0.0, cf2 = 0.0, cf3 = 0.0;

#pragma unroll
    for (int k = 0; k < 4; k++) {           // 0 north, 1 south, 2 west, 3 east
        int   j = adj[i * 4 + k];
        float L = len[i * 4 + k];
        double cc = 0.0;
        if (j >= 0 && L > 0.0f && !infl) {
            double hf   = 0.5 * (hi + (double)h[j]);
            double dphi = fabs(pi - (double)phi[j]);
            double g    = fmax(dphi, 1e-12) / (double)L;
            cc = -0.01 * pow(hf, 1.25) * (double)L * rsqrt(g);
            diag -= cc;
        }
        if (k == 0) cf0 = cc; else if (k == 1) cf1 = cc;
        else if (k == 2) cf2 = cc; else cf3 = cc;
    }

    gA[r * BSZ + a * BD + a] = infl ? 1.0f : (float)diag;
    if (a > 0)  gA[r * BSZ + a * BD + (a - 1)] = (float)cf2;   // west
    if (a < 63) gA[r * BSZ + a * BD + (a + 1)] = (float)cf3;   // east
    gCb[0][r * BSZ + a * BD + a] = (float)cf0;                 // north -> r-1
    gBb[0][r * BSZ + a * BD + a] = (float)cf1;                 // south -> r+1
    gy[i] = infl ? (float)((double)base[i] - (double)over[i]) : melt[i];
}

// ---------------------------------------------------------------------------
// K1: per eliminated block row j, Gauss-Jordan on the augmented 64x193 system
// [A | C | B | y] -> [I | ZC | ZB | Zy]. Augmented matrix lives in registers:
// 1024 threads, thread (row = tid&63, g = tid>>6) owns cols [12g, 12g+12)
// (group 15 also owns col 192 = y). Barriers are always uniform.
// ---------------------------------------------------------------------------
__global__ void __launch_bounds__(1024, 1)
k1_factor(int s, int parity)
{
    const int j   = s - 1 + 2 * s * blockIdx.x;
    const int row = threadIdx.x & 63;
    const int g   = threadIdx.x >> 6;
    const int c0  = 12 * g;

    const float* Aj = gA + j * BSZ;
    const float* Cj = gCb[parity] + j * BSZ;
    const float* Bj = gBb[parity] + j * BSZ;

    float m[13];
#pragma unroll
    for (int q = 0; q < 13; q++) {
        int c = c0 + q;
        float v = 0.0f;
        if (q < 12 || g == 15) {
            if      (c < 64)  v = Aj[row * BD + c];
            else if (c < 128) v = Cj[row * BD + (c - 64)];
            else if (c < 192) v = Bj[row * BD + (c - 128)];
            else              v = gy[j * BD + row];
        }
        m[q] = v;
    }

    __shared__ float s_piv[196];
    __shared__ float s_col[64];
    __shared__ float s_diag;
    if (threadIdx.x == 0) s_diag = m[0];
    __syncthreads();

    for (int k = 0; k < 64; k++) {
        const int gk = k / 12;
        const int qk = k - 12 * gk;

        // ---- phase A: normalize pivot row / publish pivot column ----------
        if (row == k) {
            float rinv = 1.0f / s_diag;
#pragma unroll
            for (int q = 0; q < 13; q++) m[q] *= rinv;
            *(float4*)&s_piv[c0]     = make_float4(m[0], m[1], m[2],  m[3]);
            *(float4*)&s_piv[c0 + 4] = make_float4(m[4], m[5], m[6],  m[7]);
            *(float4*)&s_piv[c0 + 8] = make_float4(m[8], m[9], m[10], m[11]);
            if (g == 15) s_piv[192] = m[12];
        } else if (g == gk) {
            float v = 0.0f;
#pragma unroll
            for (int q = 0; q < 12; q++) if (q == qk) v = m[q];
            s_col[row] = v;
        }
        __syncthreads();

        // ---- phase B: rank-1 elimination ----------------------------------
        float a = (row == k) ? 0.0f : s_col[row];
        float4 p0 = *(const float4*)&s_piv[c0];
        float4 p1 = *(const float4*)&s_piv[c0 + 4];
        float4 p2 = *(const float4*)&s_piv[c0 + 8];
        m[0] -= a * p0.x;  m[1] -= a * p0.y;  m[2]  -= a * p0.z;  m[3]  -= a * p0.w;
        m[4] -= a * p1.x;  m[5] -= a * p1.y;  m[6]  -= a * p1.z;  m[7]  -= a * p1.w;
        m[8] -= a * p2.x;  m[9] -= a * p2.y;  m[10] -= a * p2.z;  m[11] -= a * p2.w;
        if (g == 15) m[12] -= a * s_piv[192];

        if (row == k + 1) {                       // publish next pivot value
            int gk1 = (k + 1) / 12;
            if (g == gk1) {
                int qk1 = (k + 1) - 12 * gk1;
                float v = 0.0f;
#pragma unroll
                for (int q = 0; q < 12; q++) if (q == qk1) v = m[q];
                s_diag = v;
            }
        }
        __syncthreads();
    }

    // ---- write Z = [ZC | ZB | Zy] ----------------------------------------
#pragma unroll
    for (int q = 0; q < 13; q++) {
        int c = c0 + q;
        if (q < 12 || g == 15) {
            if      (c >= 64  && c < 128) gZC[j * BSZ + row * BD + (c - 64)]  = m[q];
            else if (c >= 128 && c < 192) gZB[j * BSZ + row * BD + (c - 128)] = m[q];
            else if (c == 192)            gZy[j * BD + row] = m[q];
        }
    }
}

// ---------------------------------------------------------------------------
// K2: Schur updates for each remaining row i (stride s):
//   task 0: A_i -= C_i*ZB_{i-s} + B_i*ZC_{i+s}
//   task 1: C'_i = -C_i*ZC_{i-s}
//   task 2: B'_i = -B_i*ZB_{i+s}
//   task 3: y_i -= C_i*Zy_{i-s} + B_i*Zy_{i+s}
// (i+s clamped: only i=63 lacks a right neighbor, and B_63 == 0.)
// ---------------------------------------------------------------------------
#define K2_SMEM (4 * 64 * 68 * 4)

__global__ void __launch_bounds__(256, 1)
k2_update(int s, int p)
{
    const int i    = 2 * s - 1 + 2 * s * blockIdx.x;
    const int task = blockIdx.y;
    const int jm   = i - s;
    const int jp   = (i + s > 63) ? 63 : (i + s);
    const int tid  = threadIdx.x;

    if (task == 3) {
        __shared__ float sy1[64], sy2[64];
        if (tid < 64) { sy1[tid] = gZy[jm * BD + tid]; sy2[tid] = gZy[jp * BD + tid]; }
        __syncthreads();
        if (tid < 64) {
            float acc = gy[i * BD + tid];
            const float* cp = gCb[p] + i * BSZ + tid * BD;
            const float* bp = gBb[p] + i * BSZ + tid * BD;
#pragma unroll 8
            for (int b = 0; b < 64; b++) acc -= cp[b] * sy1[b] + bp[b] * sy2[b];
            gy[i * BD + tid] = acc;
        }
        return;
    }

    extern __shared__ float sm2[];
    float* P1 = sm2;
    float* Q1 = sm2 + 64 * 68;
    float* P2 = sm2 + 2 * 64 * 68;
    float* Q2 = sm2 + 3 * 64 * 68;

    const float *p1g, *q1g, *p2g = nullptr, *q2g = nullptr;
    if (task == 0) {
        p1g = gCb[p] + i * BSZ;  q1g = gZB + jm * BSZ;
        p2g = gBb[p] + i * BSZ;  q2g = gZC + jp * BSZ;
    } else if (task == 1) {
        p1g = gCb[p] + i * BSZ;  q1g = gZC + jm * BSZ;
    } else {
        p1g = gBb[p] + i * BSZ;  q1g = gZB + jp * BSZ;
    }

    for (int e = tid; e < BSZ; e += 256) {
        int r = e >> 6, c = e & 63;
        P1[r * 68 + c] = p1g[e];
        Q1[r * 68 + c] = q1g[e];
        if (task == 0) { P2[r * 68 + c] = p2g[e]; Q2[r * 68 + c] = q2g[e]; }
    }
    __syncthreads();

    const int r0 = (tid >> 4) << 2;
    const int cc = (tid & 15) << 2;
    float acc[4][4];
#pragma unroll
    for (int u = 0; u < 4; u++)
#pragma unroll
        for (int v = 0; v < 4; v++) acc[u][v] = 0.0f;

    if (task == 0) {
        for (int k = 0; k < 64; k++) {
            float4 b1 = *(const float4*)&Q1[k * 68 + cc];
            float4 b2 = *(const float4*)&Q2[k * 68 + cc];
#pragma unroll
            for (int u = 0; u < 4; u++) {
                float a1 = P1[(r0 + u) * 68 + k];
                float a2 = P2[(r0 + u) * 68 + k];
                acc[u][0] += a1 * b1.x + a2 * b2.x;
                acc[u][1] += a1 * b1.y + a2 * b2.y;
                acc[u][2] += a1 * b1.z + a2 * b2.z;
                acc[u][3] += a1 * b1.w + a2 * b2.w;
            }
        }
        float* dst = gA + i * BSZ;
#pragma unroll
        for (int u = 0; u < 4; u++) {
            float4 o = *(float4*)&dst[(r0 + u) * BD + cc];
            o.x -= acc[u][0]; o.y -= acc[u][1]; o.z -= acc[u][2]; o.w -= acc[u][3];
            *(float4*)&dst[(r0 + u) * BD + cc] = o;
        }
    } else {
        for (int k = 0; k < 64; k++) {
            float4 b1 = *(const float4*)&Q1[k * 68 + cc];
#pragma unroll
            for (int u = 0; u < 4; u++) {
                float a1 = P1[(r0 + u) * 68 + k];
                acc[u][0] += a1 * b1.x;
                acc[u][1] += a1 * b1.y;
                acc[u][2] += a1 * b1.z;
                acc[u][3] += a1 * b1.w;
            }
        }
        float* dst = ((task == 1) ? gCb[p ^ 1] : gBb[p ^ 1]) + i * BSZ;
#pragma unroll
        for (int u = 0; u < 4; u++)
            *(float4*)&dst[(r0 + u) * BD + cc] =
                make_float4(-acc[u][0], -acc[u][1], -acc[u][2], -acc[u][3]);
    }
}

// ---------------------------------------------------------------------------
// Backsub: single CTA walks levels 7..1; x kept in shared memory.
//   x_j = Zy_j - ZC_j x_{j-s} - ZB_j x_{j+s}
// ---------------------------------------------------------------------------
__global__ void __launch_bounds__(1024, 1)
backsub_kernel(float* __restrict__ out)
{
    __shared__ float sx[NBLK * BD];
    const int tid = threadIdx.x;
    for (int e = tid; e < NBLK * BD; e += 1024) sx[e] = 0.0f;
    __syncthreads();

    for (int lev = 7; lev >= 1; lev--) {
        int s  = 1 << (lev - 1);
        int ne = (lev == 7) ? 1 : (32 >> (lev - 1));
        for (int idx = tid; idx < ne * 64; idx += 1024) {
            int t = idx >> 6, a = idx & 63;
            int j = s - 1 + 2 * s * t;
            int jm = j - s; if (jm < 0)  jm = 0;    // ZC_j == 0 there
            int jp = j + s; if (jp > 63) jp = 63;   // ZB_j == 0 there
            const float4* zc = (const float4*)(gZC + j * BSZ + a * BD);
            const float4* zb = (const float4*)(gZB + j * BSZ + a * BD);
            float s0 = 0.f, s1 = 0.f, s2 = 0.f, s3 = 0.f;
#pragma unroll
            for (int w = 0; w < 16; w++) {
                float4 c4 = zc[w], b4 = zb[w];
                s0 += c4.x * sx[jm * BD + 4 * w]     + b4.x * sx[jp * BD + 4 * w];
                s1 += c4.y * sx[jm * BD + 4 * w + 1] + b4.y * sx[jp * BD + 4 * w + 1];
                s2 += c4.z * sx[jm * BD + 4 * w + 2] + b4.z * sx[jp * BD + 4 * w + 2];
                s3 += c4.w * sx[jm * BD + 4 * w + 3] + b4.w * sx[jp * BD + 4 * w + 3];
            }
            float acc = gZy[j * BD + a] - (s0 + s1 + s2 + s3);
            sx[j * BD + a]  = acc;
            out[j * BD + a] = acc;
        }
        __syncthreads();
    }
}

// ---------------------------------------------------------------------------
// kernel_launch
// inputs: 0 sheet_thickness, 1 previous_potential, 2 base_potential,
//         3 overburden_pressure, 4 specific_melt_rate, 5 link_length[N,4],
//         6 adjacent_nodes[N,4], 7 inflow_outflow[N]
// ---------------------------------------------------------------------------
extern "C" void kernel_launch(void* const* d_in, const int* in_sizes, int n_in,
                              void* d_out, int out_size)
{
    const float* h    = (const float*)d_in[0];
    const float* phi  = (const float*)d_in[1];
    const float* base = (const float*)d_in[2];
    const float* over = (const float*)d_in[3];
    const float* melt = (const float*)d_in[4];
    const float* len  = (const float*)d_in[5];
    const int*   adj  = (const int*)  d_in[6];
    const int*   io   = (const int*)  d_in[7];
    float* out = (float*)d_out;

    static int once = []() {
        cudaFuncSetAttribute(k2_update,
                             cudaFuncAttributeMaxDynamicSharedMemorySize,
                             K2_SMEM);
        return 0;
    }();
    (void)once;

    assemble_kernel<<<32, 128>>>(h, phi, base, over, melt, len, adj, io);

    for (int lev = 1; lev <= 6; lev++) {
        int s = 1 << (lev - 1);
        int n = 32 >> (lev - 1);
        int p = (lev - 1) & 1;
        k1_factor<<<n, 1024>>>(s, p);
        k2_update<<<dim3(n, 4), 256, K2_SMEM>>>(s, p);
    }
    k1_factor<<<1, 1024>>>(64, 0);   // top row 63: Zy_63 == x_63
    backsub_kernel<<<1, 1024>>>(out);
}

// round 4
// speedup vs baseline: 35.5849x; 1.2627x over previous
#include <cuda_runtime.h>
#include <cuda_bf16.h>

// SubglacialDrainageSystem: L x = f on a 64x64 grid.
// Block cyclic reduction over the 64-block tridiagonal structure (BD=64).
// R4: k1 Gauss-Jordan is rank-4 blocked (16 iterations, double-buffered pivot
// rows/cols, 4x4 pivot-block inverse off the hot path, dead-column skip).

#define NBLK 64
#define BD   64
#define BSZ  (BD * BD)

static __device__ float gA [NBLK * BSZ];
static __device__ float gCb[2][NBLK * BSZ];
static __device__ float gBb[2][NBLK * BSZ];
static __device__ float gy [NBLK * BD];
static __device__ float gZC[NBLK * BSZ];
static __device__ float gZB[NBLK * BSZ];
static __device__ float gZy[NBLK * BD];

// ---------------------------------------------------------------------------
// Assembly
// ---------------------------------------------------------------------------
__global__ void assemble_kernel(const float* __restrict__ h,
                                const float* __restrict__ phi,
                                const float* __restrict__ base,
                                const float* __restrict__ over,
                                const float* __restrict__ melt,
                                const float* __restrict__ len,
                                const int*   __restrict__ adj,
                                const int*   __restrict__ io)
{
    int i = blockIdx.x * blockDim.x + threadIdx.x;
    if (i >= NBLK * BD) return;
    int r = i >> 6, a = i & 63;

    float4 z = make_float4(0.f, 0.f, 0.f, 0.f);
    float4* rowA = (float4*)(gA     + r * BSZ + a * BD);
    float4* rowC = (float4*)(gCb[0] + r * BSZ + a * BD);
    float4* rowB = (float4*)(gBb[0] + r * BSZ + a * BD);
#pragma unroll
    for (int b = 0; b < 16; b++) { rowA[b] = z; rowC[b] = z; rowB[b] = z; }

    const bool infl = (io[i] == 1);
    const double hi = (double)h[i];
    const double pi = (double)phi[i];
    double diag = 0.0;
    double cf0 = 0.0, cf1 = 0.0, cf2 = 0.0, cf3 = 0.0;

#pragma unroll
    for (int k = 0; k < 4; k++) {           // 0 north, 1 south, 2 west, 3 east
        int   j = adj[i * 4 + k];
        float L = len[i * 4 + k];
        double cc = 0.0;
        if (j >= 0 && L > 0.0f && !infl) {
            double hf   = 0.5 * (hi + (double)h[j]);
            double dphi = fabs(pi - (double)phi[j]);
            double g    = fmax(dphi, 1e-12) / (double)L;
            cc = -0.01 * pow(hf, 1.25) * (double)L * rsqrt(g);
            diag -= cc;
        }
        if (k == 0) cf0 = cc; else if (k == 1) cf1 = cc;
        else if (k == 2) cf2 = cc; else cf3 = cc;
    }

    gA[r * BSZ + a * BD + a] = infl ? 1.0f : (float)diag;
    if (a > 0)  gA[r * BSZ + a * BD + (a - 1)] = (float)cf2;
    if (a < 63) gA[r * BSZ + a * BD + (a + 1)] = (float)cf3;
    gCb[0][r * BSZ + a * BD + a] = (float)cf0;
    gBb[0][r * BSZ + a * BD + a] = (float)cf1;
    gy[i] = infl ? (float)((double)base[i] - (double)over[i]) : melt[i];
}

// ---------------------------------------------------------------------------
// K1: rank-4 blocked Gauss-Jordan on [A | C | B | y] (64 x 193).
// thread: row = tid&63, group g = tid>>6 owns cols [12g,12g+12) (+col192 if g=15)
// ---------------------------------------------------------------------------
__global__ void __launch_bounds__(1024, 1)
k1_factor(int s, int parity)
{
    const int j   = s - 1 + 2 * s * blockIdx.x;
    const int row = threadIdx.x & 63;
    const int g   = threadIdx.x >> 6;
    const int c0  = 12 * g;

    const float* Aj = gA + j * BSZ;
    const float* Cj = gCb[parity] + j * BSZ;
    const float* Bj = gBb[parity] + j * BSZ;

    float m[13];
#pragma unroll
    for (int q = 0; q < 13; q++) {
        int c = c0 + q;
        float v = 0.0f;
        if (q < 12 || g == 15) {
            if      (c < 64)  v = Aj[row * BD + c];
            else if (c < 128) v = Cj[row * BD + (c - 64)];
            else if (c < 192) v = Bj[row * BD + (c - 128)];
            else              v = gy[j * BD + row];
        }
        m[q] = v;
    }

    __shared__ float s_prow[2][4][200];   // raw pivot rows (double buffered)
    __shared__ float s_pcol[2][4][64];    // pivot columns, transposed
    __shared__ float s_W[2][16];          // P^{-1}, row-major

    // ---- prologue: publish window 0 --------------------------------------
    if (row < 4) {
        *(float4*)&s_prow[0][row][c0]     = make_float4(m[0], m[1], m[2],  m[3]);
        *(float4*)&s_prow[0][row][c0 + 4] = make_float4(m[4], m[5], m[6],  m[7]);
        *(float4*)&s_prow[0][row][c0 + 8] = make_float4(m[8], m[9], m[10], m[11]);
        if (g == 15) s_prow[0][row][192] = m[12];
    }
    if (g == 0) {
#pragma unroll
        for (int q = 0; q < 4; q++) s_pcol[0][q][row] = m[q];
    }
    __syncthreads();
    if (threadIdx.x == 0) {
        // 4x4 GJ inverse of P = rows 0..3 of cols 0..3
        float A4[4][4], I4[4][4];
#pragma unroll
        for (int r = 0; r < 4; r++)
#pragma unroll
            for (int t = 0; t < 4; t++) {
                A4[r][t] = s_pcol[0][t][r];
                I4[r][t] = (r == t) ? 1.0f : 0.0f;
            }
#pragma unroll
        for (int cpi = 0; cpi < 4; cpi++) {
            float rinv = __fdividef(1.0f, A4[cpi][cpi]);
#pragma unroll
            for (int t = 0; t < 4; t++) { A4[cpi][t] *= rinv; I4[cpi][t] *= rinv; }
#pragma unroll
            for (int r = 0; r < 4; r++) if (r != cpi) {
                float f = A4[r][cpi];
#pragma unroll
                for (int t = 0; t < 4; t++) {
                    A4[r][t] -= f * A4[cpi][t];
                    I4[r][t] -= f * I4[cpi][t];
                }
            }
        }
#pragma unroll
        for (int r = 0; r < 4; r++)
#pragma unroll
            for (int t = 0; t < 4; t++) s_W[0][4 * r + t] = I4[r][t];
    }
    __syncthreads();

    // ---- 16 rank-4 iterations --------------------------------------------
    for (int it = 0; it < 16; it++) {
        const int k  = 4 * it;
        const int b  = it & 1;
        const int nb = b ^ 1;
        const int kn = k + 4;
        const bool ispiv = (row >= k) && (row < kn);

        // u vector: pivot rows use +W[row-k][*]; others use -(c . W)
        float u0, u1, u2, u3;
        if (ispiv) {
            const float* wr = &s_W[b][4 * (row - k)];
            u0 = wr[0]; u1 = wr[1]; u2 = wr[2]; u3 = wr[3];
        } else {
            float cc0 = s_pcol[b][0][row];
            float cc1 = s_pcol[b][1][row];
            float cc2 = s_pcol[b][2][row];
            float cc3 = s_pcol[b][3][row];
            const float* w = s_W[b];
            u0 = -(cc0 * w[0]  + cc1 * w[4]  + cc2 * w[8]  + cc3 * w[12]);
            u1 = -(cc0 * w[1]  + cc1 * w[5]  + cc2 * w[9]  + cc3 * w[13]);
            u2 = -(cc0 * w[2]  + cc1 * w[6]  + cc2 * w[10] + cc3 * w[14]);
            u3 = -(cc0 * w[3]  + cc1 * w[7]  + cc2 * w[11] + cc3 * w[15]);
        }

        // update 3 chunks of 4 cols (skip dead A-columns: all c < k+4 dead)
#pragma unroll
        for (int ch = 0; ch < 3; ch++) {
            int cc = c0 + 4 * ch;
            if (cc + 3 >= kn) {                       // warp-uniform predicate
                float4 p0 = *(const float4*)&s_prow[b][0][cc];
                float4 p1 = *(const float4*)&s_prow[b][1][cc];
                float4 p2 = *(const float4*)&s_prow[b][2][cc];
                float4 p3 = *(const float4*)&s_prow[b][3][cc];
                float b0 = ispiv ? 0.0f : m[4 * ch + 0];
                float b1 = ispiv ? 0.0f : m[4 * ch + 1];
                float b2 = ispiv ? 0.0f : m[4 * ch + 2];
                float b3 = ispiv ? 0.0f : m[4 * ch + 3];
                m[4 * ch + 0] = b0 + u0 * p0.x + u1 * p1.x + u2 * p2.x + u3 * p3.x;
                m[4 * ch + 1] = b1 + u0 * p0.y + u1 * p1.y + u2 * p2.y + u3 * p3.y;
                m[4 * ch + 2] = b2 + u0 * p0.z + u1 * p1.z + u2 * p2.z + u3 * p3.z;
                m[4 * ch + 3] = b3 + u0 * p0.w + u1 * p1.w + u2 * p2.w + u3 * p3.w;
            }
        }
        if (g == 15) {
            float py0 = s_prow[b][0][192], py1 = s_prow[b][1][192];
            float py2 = s_prow[b][2][192], py3 = s_prow[b][3][192];
            float bb = ispiv ? 0.0f : m[12];
            m[12] = bb + u0 * py0 + u1 * py1 + u2 * py2 + u3 * py3;
        }

        if (it < 15) {
            // publish pivot rows for next window
            if (row >= kn && row < kn + 4) {
                int r2 = row - kn;
                *(float4*)&s_prow[nb][r2][c0]     = make_float4(m[0], m[1], m[2],  m[3]);
                *(float4*)&s_prow[nb][r2][c0 + 4] = make_float4(m[4], m[5], m[6],  m[7]);
                *(float4*)&s_prow[nb][r2][c0 + 8] = make_float4(m[8], m[9], m[10], m[11]);
                if (g == 15) s_prow[nb][r2][192] = m[12];
            }
            // publish pivot columns kn..kn+3 (only overlapping groups; warp-uniform)
            if (c0 + 11 >= kn && c0 <= kn + 3) {
#pragma unroll
                for (int q = 0; q < 12; q++) {
                    int t = c0 + q - kn;
                    if (t >= 0 && t < 4) s_pcol[nb][t][row] = m[q];
                }
            }
        }
        __syncthreads();

        if (it < 15) {
            if (threadIdx.x == 0) {
                float A4[4][4], I4[4][4];
#pragma unroll
                for (int r = 0; r < 4; r++)
#pragma unroll
                    for (int t = 0; t < 4; t++) {
                        A4[r][t] = s_pcol[nb][t][kn + r];
                        I4[r][t] = (r == t) ? 1.0f : 0.0f;
                    }
#pragma unroll
                for (int cpi = 0; cpi < 4; cpi++) {
                    float rinv = __fdividef(1.0f, A4[cpi][cpi]);
#pragma unroll
                    for (int t = 0; t < 4; t++) { A4[cpi][t] *= rinv; I4[cpi][t] *= rinv; }
#pragma unroll
                    for (int r = 0; r < 4; r++) if (r != cpi) {
                        float f = A4[r][cpi];
#pragma unroll
                        for (int t = 0; t < 4; t++) {
                            A4[r][t] -= f * A4[cpi][t];
                            I4[r][t] -= f * I4[cpi][t];
                        }
                    }
                }
#pragma unroll
                for (int r = 0; r < 4; r++)
#pragma unroll
                    for (int t = 0; t < 4; t++) s_W[nb][4 * r + t] = I4[r][t];
            }
            __syncthreads();
        }
    }

    // ---- write Z = [ZC | ZB | Zy] ----------------------------------------
#pragma unroll
    for (int q = 0; q < 13; q++) {
        int c = c0 + q;
        if (q < 12 || g == 15) {
            if      (c >= 64  && c < 128) gZC[j * BSZ + row * BD + (c - 64)]  = m[q];
            else if (c >= 128 && c < 192) gZB[j * BSZ + row * BD + (c - 128)] = m[q];
            else if (c == 192)            gZy[j * BD + row] = m[q];
        }
    }
}

// ---------------------------------------------------------------------------
// K2: Schur updates (unchanged from R3)
// ---------------------------------------------------------------------------
#define K2_SMEM (4 * 64 * 68 * 4)

__global__ void __launch_bounds__(256, 1)
k2_update(int s, int p)
{
    const int i    = 2 * s - 1 + 2 * s * blockIdx.x;
    const int task = blockIdx.y;
    const int jm   = i - s;
    const int jp   = (i + s > 63) ? 63 : (i + s);
    const int tid  = threadIdx.x;

    if (task == 3) {
        __shared__ float sy1[64], sy2[64];
        if (tid < 64) { sy1[tid] = gZy[jm * BD + tid]; sy2[tid] = gZy[jp * BD + tid]; }
        __syncthreads();
        if (tid < 64) {
            float acc = gy[i * BD + tid];
            const float* cp = gCb[p] + i * BSZ + tid * BD;
            const float* bp = gBb[p] + i * BSZ + tid * BD;
#pragma unroll 8
            for (int b = 0; b < 64; b++) acc -= cp[b] * sy1[b] + bp[b] * sy2[b];
            gy[i * BD + tid] = acc;
        }
        return;
    }

    extern __shared__ float sm2[];
    float* P1 = sm2;
    float* Q1 = sm2 + 64 * 68;
    float* P2 = sm2 + 2 * 64 * 68;
    float* Q2 = sm2 + 3 * 64 * 68;

    const float *p1g, *q1g, *p2g = nullptr, *q2g = nullptr;
    if (task == 0) {
        p1g = gCb[p] + i * BSZ;  q1g = gZB + jm * BSZ;
        p2g = gBb[p] + i * BSZ;  q2g = gZC + jp * BSZ;
    } else if (task == 1) {
        p1g = gCb[p] + i * BSZ;  q1g = gZC + jm * BSZ;
    } else {
        p1g = gBb[p] + i * BSZ;  q1g = gZB + jp * BSZ;
    }

    for (int e = tid; e < BSZ; e += 256) {
        int r = e >> 6, c = e & 63;
        P1[r * 68 + c] = p1g[e];
        Q1[r * 68 + c] = q1g[e];
        if (task == 0) { P2[r * 68 + c] = p2g[e]; Q2[r * 68 + c] = q2g[e]; }
    }
    __syncthreads();

    const int r0 = (tid >> 4) << 2;
    const int cc = (tid & 15) << 2;
    float acc[4][4];
#pragma unroll
    for (int u = 0; u < 4; u++)
#pragma unroll
        for (int v = 0; v < 4; v++) acc[u][v] = 0.0f;

    if (task == 0) {
        for (int k = 0; k < 64; k++) {
            float4 b1 = *(const float4*)&Q1[k * 68 + cc];
            float4 b2 = *(const float4*)&Q2[k * 68 + cc];
#pragma unroll
            for (int u = 0; u < 4; u++) {
                float a1 = P1[(r0 + u) * 68 + k];
                float a2 = P2[(r0 + u) * 68 + k];
                acc[u][0] += a1 * b1.x + a2 * b2.x;
                acc[u][1] += a1 * b1.y + a2 * b2.y;
                acc[u][2] += a1 * b1.z + a2 * b2.z;
                acc[u][3] += a1 * b1.w + a2 * b2.w;
            }
        }
        float* dst = gA + i * BSZ;
#pragma unroll
        for (int u = 0; u < 4; u++) {
            float4 o = *(float4*)&dst[(r0 + u) * BD + cc];
            o.x -= acc[u][0]; o.y -= acc[u][1]; o.z -= acc[u][2]; o.w -= acc[u][3];
            *(float4*)&dst[(r0 + u) * BD + cc] = o;
        }
    } else {
        for (int k = 0; k < 64; k++) {
            float4 b1 = *(const float4*)&Q1[k * 68 + cc];
#pragma unroll
            for (int u = 0; u < 4; u++) {
                float a1 = P1[(r0 + u) * 68 + k];
                acc[u][0] += a1 * b1.x;
                acc[u][1] += a1 * b1.y;
                acc[u][2] += a1 * b1.z;
                acc[u][3] += a1 * b1.w;
            }
        }
        float* dst = ((task == 1) ? gCb[p ^ 1] : gBb[p ^ 1]) + i * BSZ;
#pragma unroll
        for (int u = 0; u < 4; u++)
            *(float4*)&dst[(r0 + u) * BD + cc] =
                make_float4(-acc[u][0], -acc[u][1], -acc[u][2], -acc[u][3]);
    }
}

// ---------------------------------------------------------------------------
// Backsub (unchanged from R3)
// ---------------------------------------------------------------------------
__global__ void __launch_bounds__(1024, 1)
backsub_kernel(float* __restrict__ out)
{
    __shared__ float sx[NBLK * BD];
    const int tid = threadIdx.x;
    for (int e = tid; e < NBLK * BD; e += 1024) sx[e] = 0.0f;
    __syncthreads();

    for (int lev = 7; lev >= 1; lev--) {
        int s  = 1 << (lev - 1);
        int ne = (lev == 7) ? 1 : (32 >> (lev - 1));
        for (int idx = tid; idx < ne * 64; idx += 1024) {
            int t = idx >> 6, a = idx & 63;
            int j = s - 1 + 2 * s * t;
            int jm = j - s; if (jm < 0)  jm = 0;
            int jp = j + s; if (jp > 63) jp = 63;
            const float4* zc = (const float4*)(gZC + j * BSZ + a * BD);
            const float4* zb = (const float4*)(gZB + j * BSZ + a * BD);
            float s0 = 0.f, s1 = 0.f, s2 = 0.f, s3 = 0.f;
#pragma unroll
            for (int w = 0; w < 16; w++) {
                float4 c4 = zc[w], b4 = zb[w];
                s0 += c4.x * sx[jm * BD + 4 * w]     + b4.x * sx[jp * BD + 4 * w];
                s1 += c4.y * sx[jm * BD + 4 * w + 1] + b4.y * sx[jp * BD + 4 * w + 1];
                s2 += c4.z * sx[jm * BD + 4 * w + 2] + b4.z * sx[jp * BD + 4 * w + 2];
                s3 += c4.w * sx[jm * BD + 4 * w + 3] + b4.w * sx[jp * BD + 4 * w + 3];
            }
            float acc = gZy[j * BD + a] - (s0 + s1 + s2 + s3);
            sx[j * BD + a]  = acc;
            out[j * BD + a] = acc;
        }
        __syncthreads();
    }
}

// ---------------------------------------------------------------------------
// kernel_launch
// ---------------------------------------------------------------------------
extern "C" void kernel_launch(void* const* d_in, const int* in_sizes, int n_in,
                              void* d_out, int out_size)
{
    const float* h    = (const float*)d_in[0];
    const float* phi  = (const float*)d_in[1];
    const float* base = (const float*)d_in[2];
    const float* over = (const float*)d_in[3];
    const float* melt = (const float*)d_in[4];
    const float* len  = (const float*)d_in[5];
    const int*   adj  = (const int*)  d_in[6];
    const int*   io   = (const int*)  d_in[7];
    float* out = (float*)d_out;

    static int once = []() {
        cudaFuncSetAttribute(k2_update,
                             cudaFuncAttributeMaxDynamicSharedMemorySize,
                             K2_SMEM);
        return 0;
    }();
    (void)once;

    assemble_kernel<<<32, 128>>>(h, phi, base, over, melt, len, adj, io);

    for (int lev = 1; lev <= 6; lev++) {
        int s = 1 << (lev - 1);
        int n = 32 >> (lev - 1);
        int p = (lev - 1) & 1;
        k1_factor<<<n, 1024>>>(s, p);
        k2_update<<<dim3(n, 4), 256, K2_SMEM>>>(s, p);
    }
    k1_factor<<<1, 1024>>>(64, 0);
    backsub_kernel<<<1, 1024>>>(out);
}